// round 16
// baseline (speedup 1.0000x reference)
#include <cuda_runtime.h>
#include <cuda_bf16.h>
#include <math.h>

#define BB 2
#define SS 4096
#define DD 512
#define HH 8
#define DH 64
#define M_ROWS (BB*SS)   // 8192

#define TQ 64            // q rows per CTA (4 warps x 16)
#define TK 64            // kv rows per iteration
#define KPITCH 72        // K/V smem pitch in bf16 elems
#define WPITCH 136       // proj W smem pitch

// per-buffer byte offsets inside the double-buffered attn staging region
#define REG_BYTES  (TK * KPITCH * 2)           // 9216 B per array
#define OFF_KHI    0
#define OFF_KLO    (REG_BYTES)
#define OFF_VHI    (2 * REG_BYTES)
#define OFF_VLO    (3 * REG_BYTES)
#define OFF_MS     (4 * REG_BYTES)
#define BUF_BYTES  (4 * REG_BYTES + 256)       // 37120 B per buffer

#define SM_SUB 32.0f      // static softmax shift (scores bounded ~+/-50)

typedef __nv_bfloat16 bf;

// Scratch (allocation-free rule: __device__ globals). [B,H,S,d] layout.
__device__ bf g_qhi[(size_t)BB*HH*SS*DH];
__device__ bf g_qlo[(size_t)BB*HH*SS*DH];
__device__ bf g_khi[(size_t)BB*HH*SS*DH];
__device__ bf g_klo[(size_t)BB*HH*SS*DH];
__device__ bf g_vhi[(size_t)BB*HH*SS*DH];
__device__ bf g_vlo[(size_t)BB*HH*SS*DH];
__device__ float g_attn[(size_t)M_ROWS*DD];   // [B*S, D]
__device__ bf g_whi[4 * 512 * 512];           // pre-split weights hi
__device__ bf g_wlo[4 * 512 * 512];           // pre-split weights lo

__device__ __forceinline__ void mma_bf16(float* c, const unsigned* a,
                                         unsigned b0, unsigned b1)
{
    asm("mma.sync.aligned.m16n8k16.row.col.f32.bf16.bf16.f32 "
        "{%0,%1,%2,%3},{%4,%5,%6,%7},{%8,%9},{%0,%1,%2,%3};"
        : "+f"(c[0]), "+f"(c[1]), "+f"(c[2]), "+f"(c[3])
        : "r"(a[0]), "r"(a[1]), "r"(a[2]), "r"(a[3]), "r"(b0), "r"(b1));
}

// split a float pair into hi/lo bf16x2 (f0 -> low half, f1 -> high half)
__device__ __forceinline__ void split2(float f0, float f1,
                                       unsigned& hi, unsigned& lo)
{
    unsigned h;
    asm("cvt.rn.bf16x2.f32 %0, %1, %2;" : "=r"(h) : "f"(f1), "f"(f0));
    float r0 = f0 - __int_as_float(h << 16);
    float r1 = f1 - __int_as_float(h & 0xFFFF0000u);
    unsigned l;
    asm("cvt.rn.bf16x2.f32 %0, %1, %2;" : "=r"(l) : "f"(r1), "f"(r0));
    hi = h; lo = l;
}

__device__ __forceinline__ unsigned sm_u32(const void* p)
{
    return (unsigned)__cvta_generic_to_shared(p);
}

__device__ __forceinline__ void ldsm_x4(unsigned addr, unsigned& r0,
                                        unsigned& r1, unsigned& r2, unsigned& r3)
{
    asm volatile("ldmatrix.sync.aligned.m8n8.x4.shared.b16 {%0,%1,%2,%3},[%4];"
                 : "=r"(r0), "=r"(r1), "=r"(r2), "=r"(r3) : "r"(addr));
}

__device__ __forceinline__ void ldsm_x4_t(unsigned addr, unsigned& r0,
                                          unsigned& r1, unsigned& r2, unsigned& r3)
{
    asm volatile("ldmatrix.sync.aligned.m8n8.x4.trans.shared.b16 {%0,%1,%2,%3},[%4];"
                 : "=r"(r0), "=r"(r1), "=r"(r2), "=r"(r3) : "r"(addr));
}

__device__ __forceinline__ void cpa16(unsigned saddr, const void* gaddr)
{
    asm volatile("cp.async.cg.shared.global [%0], [%1], 16;\n"
                 :: "r"(saddr), "l"(gaddr));
}
__device__ __forceinline__ void cpa_commit()
{
    asm volatile("cp.async.commit_group;\n" ::: "memory");
}
__device__ __forceinline__ void cpa_wait_all()
{
    asm volatile("cp.async.wait_group 0;\n" ::: "memory");
}

// ---------------------------------------------------------------------------
// Pre-split all four weight matrices into hi/lo bf16 (once per launch).
// ---------------------------------------------------------------------------
__global__ __launch_bounds__(256) void split_w_kernel(
    const float* __restrict__ w0, const float* __restrict__ w1,
    const float* __restrict__ w2, const float* __restrict__ w3,
    bf* __restrict__ whi, bf* __restrict__ wlo)
{
    int idx = blockIdx.x * 256 + threadIdx.x;   // 0..262143
    int m   = idx >> 16;                        // matrix 0..3
    int off = (idx & 65535) * 4;
    const float* src = (m == 0) ? w0 : (m == 1) ? w1 : (m == 2) ? w2 : w3;
    float4 v = *(const float4*)(src + off);
    unsigned h0, l0, h1, l1;
    split2(v.x, v.y, h0, l0);
    split2(v.z, v.w, h1, l1);
    size_t o = (size_t)m * 262144 + off;
    *(uint2*)&whi[o] = make_uint2(h0, h1);
    *(uint2*)&wlo[o] = make_uint2(l0, l1);
}

// ---------------------------------------------------------------------------
// Tensor-core projection GEMM: out = A[8192 x 512] @ W[512 x 512] + bias.
// W pre-split in gmem (hi/lo bf16). CTA = 128x128, BK=16 double-buffered.
// MODE 0: scatter hi/lo bf16 into [B,H,S,d].  MODE 1: fp32 row-major.
// ---------------------------------------------------------------------------
template<int MODE>
__global__ __launch_bounds__(256, 2) void proj_mma(
    const float* __restrict__ A,
    const bf* __restrict__ Wh_g, const bf* __restrict__ Wl_g,
    const float* __restrict__ bias,
    bf* __restrict__ ohi, bf* __restrict__ olo, float* __restrict__ of32)
{
    __shared__ bf Ah[2][128*16], Al[2][128*16];
    __shared__ bf Wh[2][16*WPITCH], Wl[2][16*WPITCH];

    const int tid  = threadIdx.x;
    const int warp = tid >> 5, lane = tid & 31;
    const int g = lane >> 2, tg = lane & 3;
    const int n0 = blockIdx.x * 128;
    const int m0 = blockIdx.y * 128;

    const int sm  = tid >> 1;
    const int skk = (tid & 1) * 8;
    const int wkk = tid >> 4;
    const int wn8 = (tid & 15) * 8;

    const int mat = lane >> 3, r8 = lane & 7;
    const unsigned w_off = (((mat & 1) * 8 + r8) * WPITCH + (mat >> 1) * 8) * 2;

    float acc[16][4];
#pragma unroll
    for (int t = 0; t < 16; ++t)
#pragma unroll
        for (int i = 0; i < 4; ++i) acc[t][i] = 0.f;

    {
        const float* Ap = A + (size_t)(m0 + sm) * 512 + skk;
        float4 u1 = *(const float4*)Ap;
        float4 u2 = *(const float4*)(Ap + 4);
        unsigned h0, l0, h1, l1, h2, l2, h3, l3;
        split2(u1.x, u1.y, h0, l0); split2(u1.z, u1.w, h1, l1);
        split2(u2.x, u2.y, h2, l2); split2(u2.z, u2.w, h3, l3);
        *(uint4*)&Ah[0][sm * 16 + skk] = make_uint4(h0, h1, h2, h3);
        *(uint4*)&Al[0][sm * 16 + skk] = make_uint4(l0, l1, l2, l3);

        const size_t wo_g = (size_t)wkk * 512 + n0 + wn8;
        *(uint4*)&Wh[0][wkk * WPITCH + wn8] = *(const uint4*)&Wh_g[wo_g];
        *(uint4*)&Wl[0][wkk * WPITCH + wn8] = *(const uint4*)&Wl_g[wo_g];
    }
    __syncthreads();

#pragma unroll 1
    for (int c = 0; c < 32; ++c) {
        const int cur = c & 1;
        if (c + 1 < 32) {
            const int nxt = (c + 1) & 1;
            const int k0 = (c + 1) * 16;
            const float* Ap = A + (size_t)(m0 + sm) * 512 + k0 + skk;
            float4 u1 = *(const float4*)Ap;
            float4 u2 = *(const float4*)(Ap + 4);
            unsigned h0, l0, h1, l1, h2, l2, h3, l3;
            split2(u1.x, u1.y, h0, l0); split2(u1.z, u1.w, h1, l1);
            split2(u2.x, u2.y, h2, l2); split2(u2.z, u2.w, h3, l3);
            *(uint4*)&Ah[nxt][sm * 16 + skk] = make_uint4(h0, h1, h2, h3);
            *(uint4*)&Al[nxt][sm * 16 + skk] = make_uint4(l0, l1, l2, l3);

            const size_t wo_g = (size_t)(k0 + wkk) * 512 + n0 + wn8;
            *(uint4*)&Wh[nxt][wkk * WPITCH + wn8] = *(const uint4*)&Wh_g[wo_g];
            *(uint4*)&Wl[nxt][wkk * WPITCH + wn8] = *(const uint4*)&Wl_g[wo_g];
        }

        {
            const int arow = warp * 16 + g;
            unsigned ah[4], al[4];
            ah[0] = *(const unsigned*)&Ah[cur][arow * 16 + 2 * tg];
            ah[1] = *(const unsigned*)&Ah[cur][(arow + 8) * 16 + 2 * tg];
            ah[2] = *(const unsigned*)&Ah[cur][arow * 16 + 2 * tg + 8];
            ah[3] = *(const unsigned*)&Ah[cur][(arow + 8) * 16 + 2 * tg + 8];
            al[0] = *(const unsigned*)&Al[cur][arow * 16 + 2 * tg];
            al[1] = *(const unsigned*)&Al[cur][(arow + 8) * 16 + 2 * tg];
            al[2] = *(const unsigned*)&Al[cur][arow * 16 + 2 * tg + 8];
            al[3] = *(const unsigned*)&Al[cur][(arow + 8) * 16 + 2 * tg + 8];

            const unsigned whb = sm_u32(&Wh[cur][0]) + w_off;
            const unsigned wlb = sm_u32(&Wl[cur][0]) + w_off;
#pragma unroll
            for (int np = 0; np < 8; ++np) {
                const unsigned off = (np * 16) * 2;
                unsigned h0, h1, h2, h3, l0, l1, l2, l3;
                ldsm_x4_t(whb + off, h0, h1, h2, h3);
                ldsm_x4_t(wlb + off, l0, l1, l2, l3);
                mma_bf16(acc[2 * np],     ah, h0, h1);
                mma_bf16(acc[2 * np + 1], ah, h2, h3);
                mma_bf16(acc[2 * np],     ah, l0, l1);
                mma_bf16(acc[2 * np + 1], ah, l2, l3);
                mma_bf16(acc[2 * np],     al, h0, h1);
                mma_bf16(acc[2 * np + 1], al, h2, h3);
            }
        }
        __syncthreads();
    }

    const int r0 = m0 + warp * 16 + g;
    const int r1 = r0 + 8;
#pragma unroll
    for (int t = 0; t < 16; ++t) {
        const int n = n0 + 8 * t + 2 * tg;
        float2 bv = *(const float2*)&bias[n];
        float v00 = acc[t][0] + bv.x, v01 = acc[t][1] + bv.y;
        float v10 = acc[t][2] + bv.x, v11 = acc[t][3] + bv.y;
        if (MODE == 0) {
            const int h = n >> 6, dd = n & 63;
            unsigned hi0, lo0, hi1, lo1;
            split2(v00, v01, hi0, lo0);
            split2(v10, v11, hi1, lo1);
            {
                int b = r0 >> 12, s = r0 & 4095;
                size_t i0 = (((size_t)b * HH + h) * SS + s) * DH + dd;
                *(unsigned*)&ohi[i0] = hi0;
                *(unsigned*)&olo[i0] = lo0;
            }
            {
                int b = r1 >> 12, s = r1 & 4095;
                size_t i1 = (((size_t)b * HH + h) * SS + s) * DH + dd;
                *(unsigned*)&ohi[i1] = hi1;
                *(unsigned*)&olo[i1] = lo1;
            }
        } else {
            *(float2*)&of32[(size_t)r0 * 512 + n] = make_float2(v00, v01);
            *(float2*)&of32[(size_t)r1 * 512 + n] = make_float2(v10, v11);
        }
    }
}

// ---------------------------------------------------------------------------
// Tensor-core flash attention. CTA = 128 threads (4 warps), 64 q x 64 kv tile,
// DOUBLE-BUFFERED cp.async staging, 2 CTAs/SM for cross-CTA phase overlap.
// ldmatrix fragments; 3-term split MMAs; static-max softmax.
// ---------------------------------------------------------------------------
__global__ __launch_bounds__(128, 2) void attn_mma(
    const bf* __restrict__ qhi, const bf* __restrict__ qlo,
    const bf* __restrict__ khi, const bf* __restrict__ klo,
    const bf* __restrict__ vhi, const bf* __restrict__ vlo,
    const float* __restrict__ mask, float* __restrict__ out)
{
    extern __shared__ char smc[];
    const unsigned smb = sm_u32(smc);

    const int tid  = threadIdx.x;
    const int warp = tid >> 5;      // 0..3
    const int lane = tid & 31;
    const int g    = lane >> 2;
    const int tg   = lane & 3;
    const int q0   = blockIdx.x * TQ;
    const int h    = blockIdx.y;
    const int b    = blockIdx.z;

    const int mat = lane >> 3, r8 = lane & 7;
    const unsigned k_off = (((mat >> 1) * 8 + r8) * KPITCH + (mat & 1) * 8) * 2;
    const unsigned v_off = (((mat & 1) * 8 + r8) * KPITCH + (mat >> 1) * 8) * 2;

    const size_t base = ((size_t)b * HH + h) * SS * DH;
    const bf* qh = qhi + base;
    const bf* ql = qlo + base;
    const bf* kh = khi + base;
    const bf* kl = klo + base;
    const bf* vh = vhi + base;
    const bf* vl = vlo + base;
    const float* mb = mask + (size_t)b * SS;

    // staging: 64 rows / 128 threads -> 2 threads per row, 32 elems each
    const int srow = tid >> 1;
    const int scol = (tid & 1) * 32;
    const unsigned sobyte = (srow * KPITCH + scol) * 2;

    // ---- Q fragments in registers (rows r0=q0+16w+g, r1=r0+8) ----
    unsigned qah[4][4], qal[4][4];
    {
        const int r0 = q0 + warp * 16 + g;
        const int r1 = r0 + 8;
#pragma unroll
        for (int kc = 0; kc < 4; ++kc) {
            int c = kc * 16 + 2 * tg;
            qah[kc][0] = *(const unsigned*)&qh[(size_t)r0 * DH + c];
            qah[kc][1] = *(const unsigned*)&qh[(size_t)r1 * DH + c];
            qah[kc][2] = *(const unsigned*)&qh[(size_t)r0 * DH + c + 8];
            qah[kc][3] = *(const unsigned*)&qh[(size_t)r1 * DH + c + 8];
            qal[kc][0] = *(const unsigned*)&ql[(size_t)r0 * DH + c];
            qal[kc][1] = *(const unsigned*)&ql[(size_t)r1 * DH + c];
            qal[kc][2] = *(const unsigned*)&ql[(size_t)r0 * DH + c + 8];
            qal[kc][3] = *(const unsigned*)&ql[(size_t)r1 * DH + c + 8];
        }
    }

    float oacc[8][4];
#pragma unroll
    for (int t = 0; t < 8; ++t)
#pragma unroll
        for (int i = 0; i < 4; ++i) oacc[t][i] = 0.f;
    float l_a = 0.f, l_b = 0.f;

    // ---- prologue: stage tile 0 into buffer 0 ----
    {
        const unsigned bufb = smb;
        const size_t gro = (size_t)srow * DH + scol;
#pragma unroll
        for (int i = 0; i < 4; ++i) {
            cpa16(bufb + OFF_KHI + sobyte + 16 * i, &kh[gro + 8 * i]);
            cpa16(bufb + OFF_KLO + sobyte + 16 * i, &kl[gro + 8 * i]);
            cpa16(bufb + OFF_VHI + sobyte + 16 * i, &vh[gro + 8 * i]);
            cpa16(bufb + OFF_VLO + sobyte + 16 * i, &vl[gro + 8 * i]);
        }
        if (tid < 16) cpa16(bufb + OFF_MS + tid * 16, &mb[tid * 4]);
        cpa_commit();
    }

#pragma unroll 1
    for (int kt = 0; kt < SS; kt += TK) {
        const int cur = (kt >> 6) & 1;
        const unsigned bufb = smb + cur * BUF_BYTES;

        cpa_wait_all();
        __syncthreads();

        // ---- prefetch tile kt+TK into the other buffer ----
        if (kt + TK < SS) {
            const unsigned nbufb = smb + (cur ^ 1) * BUF_BYTES;
            const size_t gro = (size_t)(kt + TK + srow) * DH + scol;
#pragma unroll
            for (int i = 0; i < 4; ++i) {
                cpa16(nbufb + OFF_KHI + sobyte + 16 * i, &kh[gro + 8 * i]);
                cpa16(nbufb + OFF_KLO + sobyte + 16 * i, &kl[gro + 8 * i]);
                cpa16(nbufb + OFF_VHI + sobyte + 16 * i, &vh[gro + 8 * i]);
                cpa16(nbufb + OFF_VLO + sobyte + 16 * i, &vl[gro + 8 * i]);
            }
            if (tid < 16) cpa16(nbufb + OFF_MS + tid * 16, &mb[kt + TK + tid * 4]);
            cpa_commit();
        }

        const unsigned khi_b = bufb + OFF_KHI + k_off;
        const unsigned klo_b = bufb + OFF_KLO + k_off;
        const unsigned vhi_b = bufb + OFF_VHI + v_off;
        const unsigned vlo_b = bufb + OFF_VLO + v_off;
        const float* Ms = (const float*)(smc + cur * BUF_BYTES + OFF_MS);

        // ---- S = Q K^T (64 kv rows: 8 n-tiles, 4 ldsm pairs) ----
        float sacc[8][4];
#pragma unroll
        for (int t = 0; t < 8; ++t)
#pragma unroll
            for (int i = 0; i < 4; ++i) sacc[t][i] = 0.f;

#pragma unroll
        for (int kc = 0; kc < 4; ++kc) {
#pragma unroll
            for (int tp = 0; tp < 4; ++tp) {
                const unsigned off = (tp * 16 * KPITCH + kc * 16) * 2;
                unsigned h0, h1, h2, h3, l0, l1, l2, l3;
                ldsm_x4(khi_b + off, h0, h1, h2, h3);
                ldsm_x4(klo_b + off, l0, l1, l2, l3);
                mma_bf16(sacc[2 * tp],     qah[kc], h0, h1);
                mma_bf16(sacc[2 * tp + 1], qah[kc], h2, h3);
                mma_bf16(sacc[2 * tp],     qah[kc], l0, l1);
                mma_bf16(sacc[2 * tp + 1], qah[kc], l2, l3);
                mma_bf16(sacc[2 * tp],     qal[kc], h0, h1);
                mma_bf16(sacc[2 * tp + 1], qal[kc], h2, h3);
            }
        }

        // ---- static-max softmax: p = exp(s + mask*-1e9 - 32) ----
        float rs0 = 0.f, rs1 = 0.f, rs2 = 0.f, rs3 = 0.f;
#pragma unroll
        for (int t = 0; t < 8; ++t) {
            float2 mv = *(const float2*)&Ms[8 * t + 2 * tg];
            float m0 = fmaf(mv.x, -1e9f, -SM_SUB);
            float m1 = fmaf(mv.y, -1e9f, -SM_SUB);
            sacc[t][0] = __expf(sacc[t][0] + m0);
            sacc[t][1] = __expf(sacc[t][1] + m1);
            sacc[t][2] = __expf(sacc[t][2] + m0);
            sacc[t][3] = __expf(sacc[t][3] + m1);
            rs0 += sacc[t][0]; rs1 += sacc[t][1];
            rs2 += sacc[t][2]; rs3 += sacc[t][3];
        }
        l_a += rs0 + rs1;
        l_b += rs2 + rs3;

        // ---- O += P V ----
#pragma unroll
        for (int kc = 0; kc < 4; ++kc) {
            unsigned pah[4], pal[4];
            split2(sacc[2 * kc][0],     sacc[2 * kc][1],     pah[0], pal[0]);
            split2(sacc[2 * kc][2],     sacc[2 * kc][3],     pah[1], pal[1]);
            split2(sacc[2 * kc + 1][0], sacc[2 * kc + 1][1], pah[2], pal[2]);
            split2(sacc[2 * kc + 1][2], sacc[2 * kc + 1][3], pah[3], pal[3]);
#pragma unroll
            for (int np = 0; np < 4; ++np) {
                const unsigned off = (kc * 16 * KPITCH + np * 16) * 2;
                unsigned h0, h1, h2, h3, l0, l1, l2, l3;
                ldsm_x4_t(vhi_b + off, h0, h1, h2, h3);
                ldsm_x4_t(vlo_b + off, l0, l1, l2, l3);
                mma_bf16(oacc[2 * np],     pah, h0, h1);
                mma_bf16(oacc[2 * np + 1], pah, h2, h3);
                mma_bf16(oacc[2 * np],     pah, l0, l1);
                mma_bf16(oacc[2 * np + 1], pah, l2, l3);
                mma_bf16(oacc[2 * np],     pal, h0, h1);
                mma_bf16(oacc[2 * np + 1], pal, h2, h3);
            }
        }
    }

    // ---- epilogue: reduce l across the 4 lanes of each row, normalize ----
    {
#pragma unroll
        for (int off = 1; off < 4; off <<= 1) {
            l_a += __shfl_xor_sync(0xffffffffu, l_a, off);
            l_b += __shfl_xor_sync(0xffffffffu, l_b, off);
        }
        float inva = 1.0f / l_a, invb = 1.0f / l_b;
        const int r0 = q0 + warp * 16 + g;
        const int r1 = r0 + 8;
#pragma unroll
        for (int t = 0; t < 8; ++t) {
            int c = h * DH + 8 * t + 2 * tg;
            float2 va = {oacc[t][0] * inva, oacc[t][1] * inva};
            float2 vb = {oacc[t][2] * invb, oacc[t][3] * invb};
            *(float2*)&out[((size_t)b * SS + r0) * DD + c] = va;
            *(float2*)&out[((size_t)b * SS + r1) * DD + c] = vb;
        }
    }
}

// ---------------------------------------------------------------------------
extern "C" void kernel_launch(void* const* d_in, const int* in_sizes, int n_in,
                              void* d_out, int out_size)
{
    (void)in_sizes; (void)n_in; (void)out_size;
    const float* q    = (const float*)d_in[0];
    const float* k    = (const float*)d_in[1];
    const float* v    = (const float*)d_in[2];
    const float* mask = (const float*)d_in[3];
    const float* wq   = (const float*)d_in[4];
    const float* bq   = (const float*)d_in[5];
    const float* wk   = (const float*)d_in[6];
    const float* bk   = (const float*)d_in[7];
    const float* wv   = (const float*)d_in[8];
    const float* bv   = (const float*)d_in[9];
    const float* wo   = (const float*)d_in[10];
    const float* bo   = (const float*)d_in[11];
    float* out = (float*)d_out;

    bf *qhi, *qlo, *khi, *klo, *vhi, *vlo, *whi, *wlo;
    float* attn;
    cudaGetSymbolAddress((void**)&qhi, g_qhi);
    cudaGetSymbolAddress((void**)&qlo, g_qlo);
    cudaGetSymbolAddress((void**)&khi, g_khi);
    cudaGetSymbolAddress((void**)&klo, g_klo);
    cudaGetSymbolAddress((void**)&vhi, g_vhi);
    cudaGetSymbolAddress((void**)&vlo, g_vlo);
    cudaGetSymbolAddress((void**)&whi, g_whi);
    cudaGetSymbolAddress((void**)&wlo, g_wlo);
    cudaGetSymbolAddress((void**)&attn, g_attn);

    const int ATTN_SMEM = 2 * BUF_BYTES;  // 74240 B per CTA (2 CTAs/SM)
    static int smem_set = 0;
    if (!smem_set) {
        cudaFuncSetAttribute(attn_mma,
                             cudaFuncAttributeMaxDynamicSharedMemorySize,
                             ATTN_SMEM);
        smem_set = 1;
    }

    // pre-split all weights (wq, wk, wv, wo -> matrices 0..3)
    split_w_kernel<<<1024, 256>>>(wq, wk, wv, wo, whi, wlo);

    dim3 gproj(DD / 128, M_ROWS / 128);  // (4, 64)
    proj_mma<0><<<gproj, 256>>>(q, whi + 0 * 262144, wlo + 0 * 262144, bq,
                                qhi, qlo, nullptr);
    proj_mma<0><<<gproj, 256>>>(k, whi + 1 * 262144, wlo + 1 * 262144, bk,
                                khi, klo, nullptr);
    proj_mma<0><<<gproj, 256>>>(v, whi + 2 * 262144, wlo + 2 * 262144, bv,
                                vhi, vlo, nullptr);

    dim3 gattn(SS / TQ, HH, BB);       // (64, 8, 2)
    attn_mma<<<gattn, 128, ATTN_SMEM>>>(qhi, qlo, khi, klo, vhi, vlo,
                                        mask, attn);

    proj_mma<1><<<gproj, 256>>>(attn, whi + 3 * 262144, wlo + 3 * 262144, bo,
                                nullptr, nullptr, out);
}

// round 17
// speedup vs baseline: 1.0610x; 1.0610x over previous
#include <cuda_runtime.h>
#include <cuda_bf16.h>
#include <math.h>

#define BB 2
#define SS 4096
#define DD 512
#define HH 8
#define DH 64
#define M_ROWS (BB*SS)   // 8192

#define TQ 128
#define TK 128
#define KPITCH 72        // K/V smem pitch in bf16 elems
#define WPITCH 136       // proj W smem pitch

// per-buffer byte offsets inside the double-buffered attn staging region
#define REG_BYTES  (128 * KPITCH * 2)
#define OFF_KHI    0
#define OFF_KLO    (REG_BYTES)
#define OFF_VHI    (2 * REG_BYTES)
#define OFF_VLO    (3 * REG_BYTES)
#define OFF_MS     (4 * REG_BYTES)
#define BUF_BYTES  (4 * REG_BYTES + 512)       // 74240 B per buffer

#define SM_SUB 32.0f      // static softmax shift (scores bounded ~+/-50)

typedef __nv_bfloat16 bf;

// Scratch (allocation-free rule: __device__ globals). [B,H,S,d] layout.
__device__ bf g_qhi[(size_t)BB*HH*SS*DH];
__device__ bf g_qlo[(size_t)BB*HH*SS*DH];
__device__ bf g_khi[(size_t)BB*HH*SS*DH];
__device__ bf g_klo[(size_t)BB*HH*SS*DH];
__device__ bf g_vhi[(size_t)BB*HH*SS*DH];
__device__ bf g_vlo[(size_t)BB*HH*SS*DH];
__device__ bf g_ahi[(size_t)M_ROWS*DD];       // attn out hi  [B*S, D]
__device__ bf g_alo[(size_t)M_ROWS*DD];       // attn out lo
__device__ bf g_whi[4 * 512 * 512];           // pre-split weights hi
__device__ bf g_wlo[4 * 512 * 512];           // pre-split weights lo

__device__ __forceinline__ void mma_bf16(float* c, const unsigned* a,
                                         unsigned b0, unsigned b1)
{
    asm("mma.sync.aligned.m16n8k16.row.col.f32.bf16.bf16.f32 "
        "{%0,%1,%2,%3},{%4,%5,%6,%7},{%8,%9},{%0,%1,%2,%3};"
        : "+f"(c[0]), "+f"(c[1]), "+f"(c[2]), "+f"(c[3])
        : "r"(a[0]), "r"(a[1]), "r"(a[2]), "r"(a[3]), "r"(b0), "r"(b1));
}

// split a float pair into hi/lo bf16x2 (f0 -> low half, f1 -> high half)
__device__ __forceinline__ void split2(float f0, float f1,
                                       unsigned& hi, unsigned& lo)
{
    unsigned h;
    asm("cvt.rn.bf16x2.f32 %0, %1, %2;" : "=r"(h) : "f"(f1), "f"(f0));
    float r0 = f0 - __int_as_float(h << 16);
    float r1 = f1 - __int_as_float(h & 0xFFFF0000u);
    unsigned l;
    asm("cvt.rn.bf16x2.f32 %0, %1, %2;" : "=r"(l) : "f"(r1), "f"(r0));
    hi = h; lo = l;
}

__device__ __forceinline__ unsigned sm_u32(const void* p)
{
    return (unsigned)__cvta_generic_to_shared(p);
}

__device__ __forceinline__ void ldsm_x4(unsigned addr, unsigned& r0,
                                        unsigned& r1, unsigned& r2, unsigned& r3)
{
    asm volatile("ldmatrix.sync.aligned.m8n8.x4.shared.b16 {%0,%1,%2,%3},[%4];"
                 : "=r"(r0), "=r"(r1), "=r"(r2), "=r"(r3) : "r"(addr));
}

__device__ __forceinline__ void ldsm_x4_t(unsigned addr, unsigned& r0,
                                          unsigned& r1, unsigned& r2, unsigned& r3)
{
    asm volatile("ldmatrix.sync.aligned.m8n8.x4.trans.shared.b16 {%0,%1,%2,%3},[%4];"
                 : "=r"(r0), "=r"(r1), "=r"(r2), "=r"(r3) : "r"(addr));
}

__device__ __forceinline__ void cpa16(unsigned saddr, const void* gaddr)
{
    asm volatile("cp.async.cg.shared.global [%0], [%1], 16;\n"
                 :: "r"(saddr), "l"(gaddr));
}
__device__ __forceinline__ void cpa_commit()
{
    asm volatile("cp.async.commit_group;\n" ::: "memory");
}
__device__ __forceinline__ void cpa_wait_all()
{
    asm volatile("cp.async.wait_group 0;\n" ::: "memory");
}

// ---------------------------------------------------------------------------
// Pre-split all four weight matrices into hi/lo bf16 (once per launch).
// ---------------------------------------------------------------------------
__global__ __launch_bounds__(256) void split_w_kernel(
    const float* __restrict__ w0, const float* __restrict__ w1,
    const float* __restrict__ w2, const float* __restrict__ w3,
    bf* __restrict__ whi, bf* __restrict__ wlo)
{
    int idx = blockIdx.x * 256 + threadIdx.x;   // 0..262143
    int m   = idx >> 16;                        // matrix 0..3
    int off = (idx & 65535) * 4;
    const float* src = (m == 0) ? w0 : (m == 1) ? w1 : (m == 2) ? w2 : w3;
    float4 v = *(const float4*)(src + off);
    unsigned h0, l0, h1, l1;
    split2(v.x, v.y, h0, l0);
    split2(v.z, v.w, h1, l1);
    size_t o = (size_t)m * 262144 + off;
    *(uint2*)&whi[o] = make_uint2(h0, h1);
    *(uint2*)&wlo[o] = make_uint2(l0, l1);
}

// ---------------------------------------------------------------------------
// Fused Q/K/V projection: grid.z = 0/1/2 selects (A, W, bias, outputs).
// out = A[8192 x 512] @ W + bias, scattered as hi/lo bf16 into [B,H,S,d].
// CTA = 128x128, BK=16 double-buffered, 768 CTAs total (one launch).
// ---------------------------------------------------------------------------
__global__ __launch_bounds__(256, 2) void proj_qkv(
    const float* __restrict__ Aq, const float* __restrict__ Ak,
    const float* __restrict__ Av,
    const float* __restrict__ bq, const float* __restrict__ bk,
    const float* __restrict__ bv)
{
    __shared__ bf Ah[2][128*16], Al[2][128*16];
    __shared__ bf Wh[2][16*WPITCH], Wl[2][16*WPITCH];

    const int z = blockIdx.z;
    const float* A    = (z == 0) ? Aq : (z == 1) ? Ak : Av;
    const float* bias = (z == 0) ? bq : (z == 1) ? bk : bv;
    const bf* Wh_g = g_whi + (size_t)z * 262144;
    const bf* Wl_g = g_wlo + (size_t)z * 262144;
    bf* ohi = (z == 0) ? g_qhi : (z == 1) ? g_khi : g_vhi;
    bf* olo = (z == 0) ? g_qlo : (z == 1) ? g_klo : g_vlo;

    const int tid  = threadIdx.x;
    const int warp = tid >> 5, lane = tid & 31;
    const int g = lane >> 2, tg = lane & 3;
    const int n0 = blockIdx.x * 128;
    const int m0 = blockIdx.y * 128;

    const int sm  = tid >> 1;
    const int skk = (tid & 1) * 8;
    const int wkk = tid >> 4;
    const int wn8 = (tid & 15) * 8;

    const int mat = lane >> 3, r8 = lane & 7;
    const unsigned w_off = (((mat & 1) * 8 + r8) * WPITCH + (mat >> 1) * 8) * 2;

    float acc[16][4];
#pragma unroll
    for (int t = 0; t < 16; ++t)
#pragma unroll
        for (int i = 0; i < 4; ++i) acc[t][i] = 0.f;

    {
        const float* Ap = A + (size_t)(m0 + sm) * 512 + skk;
        float4 u1 = *(const float4*)Ap;
        float4 u2 = *(const float4*)(Ap + 4);
        unsigned h0, l0, h1, l1, h2, l2, h3, l3;
        split2(u1.x, u1.y, h0, l0); split2(u1.z, u1.w, h1, l1);
        split2(u2.x, u2.y, h2, l2); split2(u2.z, u2.w, h3, l3);
        *(uint4*)&Ah[0][sm * 16 + skk] = make_uint4(h0, h1, h2, h3);
        *(uint4*)&Al[0][sm * 16 + skk] = make_uint4(l0, l1, l2, l3);

        const size_t wo_g = (size_t)wkk * 512 + n0 + wn8;
        *(uint4*)&Wh[0][wkk * WPITCH + wn8] = *(const uint4*)&Wh_g[wo_g];
        *(uint4*)&Wl[0][wkk * WPITCH + wn8] = *(const uint4*)&Wl_g[wo_g];
    }
    __syncthreads();

#pragma unroll 1
    for (int c = 0; c < 32; ++c) {
        const int cur = c & 1;
        if (c + 1 < 32) {
            const int nxt = (c + 1) & 1;
            const int k0 = (c + 1) * 16;
            const float* Ap = A + (size_t)(m0 + sm) * 512 + k0 + skk;
            float4 u1 = *(const float4*)Ap;
            float4 u2 = *(const float4*)(Ap + 4);
            unsigned h0, l0, h1, l1, h2, l2, h3, l3;
            split2(u1.x, u1.y, h0, l0); split2(u1.z, u1.w, h1, l1);
            split2(u2.x, u2.y, h2, l2); split2(u2.z, u2.w, h3, l3);
            *(uint4*)&Ah[nxt][sm * 16 + skk] = make_uint4(h0, h1, h2, h3);
            *(uint4*)&Al[nxt][sm * 16 + skk] = make_uint4(l0, l1, l2, l3);

            const size_t wo_g = (size_t)(k0 + wkk) * 512 + n0 + wn8;
            *(uint4*)&Wh[nxt][wkk * WPITCH + wn8] = *(const uint4*)&Wh_g[wo_g];
            *(uint4*)&Wl[nxt][wkk * WPITCH + wn8] = *(const uint4*)&Wl_g[wo_g];
        }

        {
            const int arow = warp * 16 + g;
            unsigned ah[4], al[4];
            ah[0] = *(const unsigned*)&Ah[cur][arow * 16 + 2 * tg];
            ah[1] = *(const unsigned*)&Ah[cur][(arow + 8) * 16 + 2 * tg];
            ah[2] = *(const unsigned*)&Ah[cur][arow * 16 + 2 * tg + 8];
            ah[3] = *(const unsigned*)&Ah[cur][(arow + 8) * 16 + 2 * tg + 8];
            al[0] = *(const unsigned*)&Al[cur][arow * 16 + 2 * tg];
            al[1] = *(const unsigned*)&Al[cur][(arow + 8) * 16 + 2 * tg];
            al[2] = *(const unsigned*)&Al[cur][arow * 16 + 2 * tg + 8];
            al[3] = *(const unsigned*)&Al[cur][(arow + 8) * 16 + 2 * tg + 8];

            const unsigned whb = sm_u32(&Wh[cur][0]) + w_off;
            const unsigned wlb = sm_u32(&Wl[cur][0]) + w_off;
#pragma unroll
            for (int np = 0; np < 8; ++np) {
                const unsigned off = (np * 16) * 2;
                unsigned h0, h1, h2, h3, l0, l1, l2, l3;
                ldsm_x4_t(whb + off, h0, h1, h2, h3);
                ldsm_x4_t(wlb + off, l0, l1, l2, l3);
                mma_bf16(acc[2 * np],     ah, h0, h1);
                mma_bf16(acc[2 * np + 1], ah, h2, h3);
                mma_bf16(acc[2 * np],     ah, l0, l1);
                mma_bf16(acc[2 * np + 1], ah, l2, l3);
                mma_bf16(acc[2 * np],     al, h0, h1);
                mma_bf16(acc[2 * np + 1], al, h2, h3);
            }
        }
        __syncthreads();
    }

    const int r0 = m0 + warp * 16 + g;
    const int r1 = r0 + 8;
#pragma unroll
    for (int t = 0; t < 16; ++t) {
        const int n = n0 + 8 * t + 2 * tg;
        float2 bv2 = *(const float2*)&bias[n];
        float v00 = acc[t][0] + bv2.x, v01 = acc[t][1] + bv2.y;
        float v10 = acc[t][2] + bv2.x, v11 = acc[t][3] + bv2.y;
        const int hh = n >> 6, dd = n & 63;
        unsigned hi0, lo0, hi1, lo1;
        split2(v00, v01, hi0, lo0);
        split2(v10, v11, hi1, lo1);
        {
            int b = r0 >> 12, s = r0 & 4095;
            size_t i0 = (((size_t)b * HH + hh) * SS + s) * DH + dd;
            *(unsigned*)&ohi[i0] = hi0;
            *(unsigned*)&olo[i0] = lo0;
        }
        {
            int b = r1 >> 12, s = r1 & 4095;
            size_t i1 = (((size_t)b * HH + hh) * SS + s) * DH + dd;
            *(unsigned*)&ohi[i1] = hi1;
            *(unsigned*)&olo[i1] = lo1;
        }
    }
}

// ---------------------------------------------------------------------------
// Output projection: A pre-split in gmem (attn output hi/lo bf16).
// out(fp32 row-major) = A @ W + bias.
// ---------------------------------------------------------------------------
__global__ __launch_bounds__(256, 2) void proj_o(
    const bf* __restrict__ Ah_g, const bf* __restrict__ Al_g,
    const bf* __restrict__ Wh_g, const bf* __restrict__ Wl_g,
    const float* __restrict__ bias, float* __restrict__ of32)
{
    __shared__ bf Ah[2][128*16], Al[2][128*16];
    __shared__ bf Wh[2][16*WPITCH], Wl[2][16*WPITCH];

    const int tid  = threadIdx.x;
    const int warp = tid >> 5, lane = tid & 31;
    const int g = lane >> 2, tg = lane & 3;
    const int n0 = blockIdx.x * 128;
    const int m0 = blockIdx.y * 128;

    const int sm  = tid >> 1;
    const int skk = (tid & 1) * 8;
    const int wkk = tid >> 4;
    const int wn8 = (tid & 15) * 8;

    const int mat = lane >> 3, r8 = lane & 7;
    const unsigned w_off = (((mat & 1) * 8 + r8) * WPITCH + (mat >> 1) * 8) * 2;

    float acc[16][4];
#pragma unroll
    for (int t = 0; t < 16; ++t)
#pragma unroll
        for (int i = 0; i < 4; ++i) acc[t][i] = 0.f;

    {
        const size_t ao_g = (size_t)(m0 + sm) * 512 + skk;
        *(uint4*)&Ah[0][sm * 16 + skk] = *(const uint4*)&Ah_g[ao_g];
        *(uint4*)&Al[0][sm * 16 + skk] = *(const uint4*)&Al_g[ao_g];
        const size_t wo_g = (size_t)wkk * 512 + n0 + wn8;
        *(uint4*)&Wh[0][wkk * WPITCH + wn8] = *(const uint4*)&Wh_g[wo_g];
        *(uint4*)&Wl[0][wkk * WPITCH + wn8] = *(const uint4*)&Wl_g[wo_g];
    }
    __syncthreads();

#pragma unroll 1
    for (int c = 0; c < 32; ++c) {
        const int cur = c & 1;
        if (c + 1 < 32) {
            const int nxt = (c + 1) & 1;
            const int k0 = (c + 1) * 16;
            const size_t ao_g = (size_t)(m0 + sm) * 512 + k0 + skk;
            *(uint4*)&Ah[nxt][sm * 16 + skk] = *(const uint4*)&Ah_g[ao_g];
            *(uint4*)&Al[nxt][sm * 16 + skk] = *(const uint4*)&Al_g[ao_g];
            const size_t wo_g = (size_t)(k0 + wkk) * 512 + n0 + wn8;
            *(uint4*)&Wh[nxt][wkk * WPITCH + wn8] = *(const uint4*)&Wh_g[wo_g];
            *(uint4*)&Wl[nxt][wkk * WPITCH + wn8] = *(const uint4*)&Wl_g[wo_g];
        }

        {
            const int arow = warp * 16 + g;
            unsigned ah[4], al[4];
            ah[0] = *(const unsigned*)&Ah[cur][arow * 16 + 2 * tg];
            ah[1] = *(const unsigned*)&Ah[cur][(arow + 8) * 16 + 2 * tg];
            ah[2] = *(const unsigned*)&Ah[cur][arow * 16 + 2 * tg + 8];
            ah[3] = *(const unsigned*)&Ah[cur][(arow + 8) * 16 + 2 * tg + 8];
            al[0] = *(const unsigned*)&Al[cur][arow * 16 + 2 * tg];
            al[1] = *(const unsigned*)&Al[cur][(arow + 8) * 16 + 2 * tg];
            al[2] = *(const unsigned*)&Al[cur][arow * 16 + 2 * tg + 8];
            al[3] = *(const unsigned*)&Al[cur][(arow + 8) * 16 + 2 * tg + 8];

            const unsigned whb = sm_u32(&Wh[cur][0]) + w_off;
            const unsigned wlb = sm_u32(&Wl[cur][0]) + w_off;
#pragma unroll
            for (int np = 0; np < 8; ++np) {
                const unsigned off = (np * 16) * 2;
                unsigned h0, h1, h2, h3, l0, l1, l2, l3;
                ldsm_x4_t(whb + off, h0, h1, h2, h3);
                ldsm_x4_t(wlb + off, l0, l1, l2, l3);
                mma_bf16(acc[2 * np],     ah, h0, h1);
                mma_bf16(acc[2 * np + 1], ah, h2, h3);
                mma_bf16(acc[2 * np],     ah, l0, l1);
                mma_bf16(acc[2 * np + 1], ah, l2, l3);
                mma_bf16(acc[2 * np],     al, h0, h1);
                mma_bf16(acc[2 * np + 1], al, h2, h3);
            }
        }
        __syncthreads();
    }

    const int r0 = m0 + warp * 16 + g;
    const int r1 = r0 + 8;
#pragma unroll
    for (int t = 0; t < 16; ++t) {
        const int n = n0 + 8 * t + 2 * tg;
        float2 bv2 = *(const float2*)&bias[n];
        *(float2*)&of32[(size_t)r0 * 512 + n] =
            make_float2(acc[t][0] + bv2.x, acc[t][1] + bv2.y);
        *(float2*)&of32[(size_t)r1 * 512 + n] =
            make_float2(acc[t][2] + bv2.x, acc[t][3] + bv2.y);
    }
}

// ---------------------------------------------------------------------------
// Tensor-core flash attention (R14 structure). 128 q x 128 kv per iter,
// 8 warps, cp.async double-buffered staging, static-max softmax.
// Output written as hi/lo bf16 (pre-split for proj_o).
// ---------------------------------------------------------------------------
__global__ __launch_bounds__(256, 1) void attn_mma(
    const bf* __restrict__ qhi, const bf* __restrict__ qlo,
    const bf* __restrict__ khi, const bf* __restrict__ klo,
    const bf* __restrict__ vhi, const bf* __restrict__ vlo,
    const float* __restrict__ mask,
    bf* __restrict__ ahi, bf* __restrict__ alo)
{
    extern __shared__ char smc[];
    const unsigned smb = sm_u32(smc);

    const int tid  = threadIdx.x;
    const int warp = tid >> 5;
    const int lane = tid & 31;
    const int g    = lane >> 2;
    const int tg   = lane & 3;
    const int q0   = blockIdx.x * TQ;
    const int h    = blockIdx.y;
    const int b    = blockIdx.z;

    const int mat = lane >> 3, r8 = lane & 7;
    const unsigned k_off = (((mat >> 1) * 8 + r8) * KPITCH + (mat & 1) * 8) * 2;
    const unsigned v_off = (((mat & 1) * 8 + r8) * KPITCH + (mat >> 1) * 8) * 2;

    const size_t base = ((size_t)b * HH + h) * SS * DH;
    const bf* qh = qhi + base;
    const bf* ql = qlo + base;
    const bf* kh = khi + base;
    const bf* kl = klo + base;
    const bf* vh = vhi + base;
    const bf* vl = vlo + base;
    const float* mb = mask + (size_t)b * SS;

    const int srow = tid >> 1;
    const int scol = (tid & 1) * 32;
    const unsigned sobyte = (srow * KPITCH + scol) * 2;

    // ---- Q fragments in registers ----
    unsigned qah[4][4], qal[4][4];
    {
        const int r0 = q0 + warp * 16 + g;
        const int r1 = r0 + 8;
#pragma unroll
        for (int kc = 0; kc < 4; ++kc) {
            int c = kc * 16 + 2 * tg;
            qah[kc][0] = *(const unsigned*)&qh[(size_t)r0 * DH + c];
            qah[kc][1] = *(const unsigned*)&qh[(size_t)r1 * DH + c];
            qah[kc][2] = *(const unsigned*)&qh[(size_t)r0 * DH + c + 8];
            qah[kc][3] = *(const unsigned*)&qh[(size_t)r1 * DH + c + 8];
            qal[kc][0] = *(const unsigned*)&ql[(size_t)r0 * DH + c];
            qal[kc][1] = *(const unsigned*)&ql[(size_t)r1 * DH + c];
            qal[kc][2] = *(const unsigned*)&ql[(size_t)r0 * DH + c + 8];
            qal[kc][3] = *(const unsigned*)&ql[(size_t)r1 * DH + c + 8];
        }
    }

    float oacc[8][4];
#pragma unroll
    for (int t = 0; t < 8; ++t)
#pragma unroll
        for (int i = 0; i < 4; ++i) oacc[t][i] = 0.f;
    float l_a = 0.f, l_b = 0.f;

    // ---- prologue: stage tile 0 into buffer 0 ----
    {
        const unsigned bufb = smb;
        const size_t gro = (size_t)srow * DH + scol;
#pragma unroll
        for (int i = 0; i < 4; ++i) {
            cpa16(bufb + OFF_KHI + sobyte + 16 * i, &kh[gro + 8 * i]);
            cpa16(bufb + OFF_KLO + sobyte + 16 * i, &kl[gro + 8 * i]);
            cpa16(bufb + OFF_VHI + sobyte + 16 * i, &vh[gro + 8 * i]);
            cpa16(bufb + OFF_VLO + sobyte + 16 * i, &vl[gro + 8 * i]);
        }
        if (tid < 32) cpa16(bufb + OFF_MS + tid * 16, &mb[tid * 4]);
        cpa_commit();
    }

#pragma unroll 1
    for (int kt = 0; kt < SS; kt += TK) {
        const int cur = (kt >> 7) & 1;
        const unsigned bufb = smb + cur * BUF_BYTES;

        cpa_wait_all();
        __syncthreads();

        // ---- prefetch tile kt+TK into the other buffer ----
        if (kt + TK < SS) {
            const unsigned nbufb = smb + (cur ^ 1) * BUF_BYTES;
            const size_t gro = (size_t)(kt + TK + srow) * DH + scol;
#pragma unroll
            for (int i = 0; i < 4; ++i) {
                cpa16(nbufb + OFF_KHI + sobyte + 16 * i, &kh[gro + 8 * i]);
                cpa16(nbufb + OFF_KLO + sobyte + 16 * i, &kl[gro + 8 * i]);
                cpa16(nbufb + OFF_VHI + sobyte + 16 * i, &vh[gro + 8 * i]);
                cpa16(nbufb + OFF_VLO + sobyte + 16 * i, &vl[gro + 8 * i]);
            }
            if (tid < 32) cpa16(nbufb + OFF_MS + tid * 16, &mb[kt + TK + tid * 4]);
            cpa_commit();
        }

        const unsigned khi_b = bufb + OFF_KHI + k_off;
        const unsigned klo_b = bufb + OFF_KLO + k_off;
        const unsigned vhi_b = bufb + OFF_VHI + v_off;
        const unsigned vlo_b = bufb + OFF_VLO + v_off;
        const float* Ms = (const float*)(smc + cur * BUF_BYTES + OFF_MS);

        // ---- S = Q K^T ----
        float sacc[16][4];
#pragma unroll
        for (int t = 0; t < 16; ++t)
#pragma unroll
            for (int i = 0; i < 4; ++i) sacc[t][i] = 0.f;

#pragma unroll
        for (int kc = 0; kc < 4; ++kc) {
#pragma unroll
            for (int tp = 0; tp < 8; ++tp) {
                const unsigned off = (tp * 16 * KPITCH + kc * 16) * 2;
                unsigned h0, h1, h2, h3, l0, l1, l2, l3;
                ldsm_x4(khi_b + off, h0, h1, h2, h3);
                ldsm_x4(klo_b + off, l0, l1, l2, l3);
                mma_bf16(sacc[2 * tp],     qah[kc], h0, h1);
                mma_bf16(sacc[2 * tp + 1], qah[kc], h2, h3);
                mma_bf16(sacc[2 * tp],     qah[kc], l0, l1);
                mma_bf16(sacc[2 * tp + 1], qah[kc], l2, l3);
                mma_bf16(sacc[2 * tp],     qal[kc], h0, h1);
                mma_bf16(sacc[2 * tp + 1], qal[kc], h2, h3);
            }
        }

        // ---- static-max softmax: p = exp(s + mask*-1e9 - 32) ----
        float rs0 = 0.f, rs1 = 0.f, rs2 = 0.f, rs3 = 0.f;
#pragma unroll
        for (int t = 0; t < 16; ++t) {
            float2 mv = *(const float2*)&Ms[8 * t + 2 * tg];
            float m0 = fmaf(mv.x, -1e9f, -SM_SUB);
            float m1 = fmaf(mv.y, -1e9f, -SM_SUB);
            sacc[t][0] = __expf(sacc[t][0] + m0);
            sacc[t][1] = __expf(sacc[t][1] + m1);
            sacc[t][2] = __expf(sacc[t][2] + m0);
            sacc[t][3] = __expf(sacc[t][3] + m1);
            rs0 += sacc[t][0]; rs1 += sacc[t][1];
            rs2 += sacc[t][2]; rs3 += sacc[t][3];
        }
        l_a += rs0 + rs1;
        l_b += rs2 + rs3;

        // ---- O += P V ----
#pragma unroll
        for (int kc = 0; kc < 8; ++kc) {
            unsigned pah[4], pal[4];
            split2(sacc[2 * kc][0],     sacc[2 * kc][1],     pah[0], pal[0]);
            split2(sacc[2 * kc][2],     sacc[2 * kc][3],     pah[1], pal[1]);
            split2(sacc[2 * kc + 1][0], sacc[2 * kc + 1][1], pah[2], pal[2]);
            split2(sacc[2 * kc + 1][2], sacc[2 * kc + 1][3], pah[3], pal[3]);
#pragma unroll
            for (int np = 0; np < 4; ++np) {
                const unsigned off = (kc * 16 * KPITCH + np * 16) * 2;
                unsigned h0, h1, h2, h3, l0, l1, l2, l3;
                ldsm_x4_t(vhi_b + off, h0, h1, h2, h3);
                ldsm_x4_t(vlo_b + off, l0, l1, l2, l3);
                mma_bf16(oacc[2 * np],     pah, h0, h1);
                mma_bf16(oacc[2 * np + 1], pah, h2, h3);
                mma_bf16(oacc[2 * np],     pah, l0, l1);
                mma_bf16(oacc[2 * np + 1], pah, l2, l3);
                mma_bf16(oacc[2 * np],     pal, h0, h1);
                mma_bf16(oacc[2 * np + 1], pal, h2, h3);
            }
        }
    }

    // ---- epilogue: reduce l, normalize, write hi/lo bf16 [B*S, D] ----
    {
#pragma unroll
        for (int off = 1; off < 4; off <<= 1) {
            l_a += __shfl_xor_sync(0xffffffffu, l_a, off);
            l_b += __shfl_xor_sync(0xffffffffu, l_b, off);
        }
        float inva = 1.0f / l_a, invb = 1.0f / l_b;
        const int r0 = q0 + warp * 16 + g;
        const int r1 = r0 + 8;
        const size_t row0 = ((size_t)b * SS + r0) * DD;
        const size_t row1 = ((size_t)b * SS + r1) * DD;
#pragma unroll
        for (int t = 0; t < 8; ++t) {
            int c = h * DH + 8 * t + 2 * tg;
            unsigned hi0, lo0, hi1, lo1;
            split2(oacc[t][0] * inva, oacc[t][1] * inva, hi0, lo0);
            split2(oacc[t][2] * invb, oacc[t][3] * invb, hi1, lo1);
            *(unsigned*)&ahi[row0 + c] = hi0;
            *(unsigned*)&alo[row0 + c] = lo0;
            *(unsigned*)&ahi[row1 + c] = hi1;
            *(unsigned*)&alo[row1 + c] = lo1;
        }
    }
}

// ---------------------------------------------------------------------------
extern "C" void kernel_launch(void* const* d_in, const int* in_sizes, int n_in,
                              void* d_out, int out_size)
{
    (void)in_sizes; (void)n_in; (void)out_size;
    const float* q    = (const float*)d_in[0];
    const float* k    = (const float*)d_in[1];
    const float* v    = (const float*)d_in[2];
    const float* mask = (const float*)d_in[3];
    const float* wq   = (const float*)d_in[4];
    const float* bq   = (const float*)d_in[5];
    const float* wk   = (const float*)d_in[6];
    const float* bk   = (const float*)d_in[7];
    const float* wv   = (const float*)d_in[8];
    const float* bv   = (const float*)d_in[9];
    const float* wo   = (const float*)d_in[10];
    const float* bo   = (const float*)d_in[11];
    float* out = (float*)d_out;

    bf *qhi, *qlo, *khi, *klo, *vhi, *vlo, *whi, *wlo, *ahi, *alo;
    cudaGetSymbolAddress((void**)&qhi, g_qhi);
    cudaGetSymbolAddress((void**)&qlo, g_qlo);
    cudaGetSymbolAddress((void**)&khi, g_khi);
    cudaGetSymbolAddress((void**)&klo, g_klo);
    cudaGetSymbolAddress((void**)&vhi, g_vhi);
    cudaGetSymbolAddress((void**)&vlo, g_vlo);
    cudaGetSymbolAddress((void**)&whi, g_whi);
    cudaGetSymbolAddress((void**)&wlo, g_wlo);
    cudaGetSymbolAddress((void**)&ahi, g_ahi);
    cudaGetSymbolAddress((void**)&alo, g_alo);

    const int ATTN_SMEM = 2 * BUF_BYTES;  // 148480 B
    static int smem_set = 0;
    if (!smem_set) {
        cudaFuncSetAttribute(attn_mma,
                             cudaFuncAttributeMaxDynamicSharedMemorySize,
                             ATTN_SMEM);
        smem_set = 1;
    }

    // pre-split all weights (wq, wk, wv, wo -> matrices 0..3)
    split_w_kernel<<<1024, 256>>>(wq, wk, wv, wo, whi, wlo);

    // fused Q/K/V projections: one launch, 768 CTAs
    dim3 gqkv(DD / 128, M_ROWS / 128, 3);  // (4, 64, 3)
    proj_qkv<<<gqkv, 256>>>(q, k, v, bq, bk, bv);

    dim3 gattn(SS / TQ, HH, BB);           // (32, 8, 2)
    attn_mma<<<gattn, 256, ATTN_SMEM>>>(qhi, qlo, khi, klo, vhi, vlo,
                                        mask, ahi, alo);

    dim3 gproj(DD / 128, M_ROWS / 128);    // (4, 64)
    proj_o<<<gproj, 256>>>(ahi, alo, whi + 3 * 262144, wlo + 3 * 262144,
                           bo, out);
}